// round 11
// baseline (speedup 1.0000x reference)
#include <cuda_runtime.h>
#include <cstdint>

// Problem constants (fixed by reference)
#define NN   1000      // nodes
#define DD   256       // feature dim
#define NE   4000      // edges = N*K (== P2 block of paths)
#define P3_OFF 4000
#define P4_OFF 20000
#define PT   84000     // total paths
#define PS_GRID 500     // path_sum block-units (8 e0 each)
#define PSUM_ROWS 2000  // 4 partial rows per path_sum unit
#define AGG_BLOCKS 64   // k-chunks of 4

// GEMM smem pipeline config
#define NSTAGE 4
#define A_STRIDE 20                 // floats per A smem row (16 + 4 pad)
#define B_STRIDE 136                // floats per B smem k-row (128 + 8 pad)
#define A_TILE (128 * A_STRIDE)     // 2560 floats / stage
#define B_TILE (16 * B_STRIDE)      // 2176 floats / stage
#define GEMM_SMEM ((NSTAGE * (A_TILE + B_TILE)) * 4)   // 75776 bytes

// Device scratch (static globals: no allocation allowed)
__device__ float g_h1[6 * NN * DD];       // nf @ W1 halves: [s*2+half][node][d]
__device__ float g_H[3 * NE * DD];        // relu(h_cur[src] + h_nxt[dst] + b1)
__device__ float g_G[3 * NE * DD];        // H_s @ Wc[s] + bc[s]
__device__ float g_Wc[3 * DD * DD];       // W2[s] @ Wa1_s
__device__ float g_Wsc[DD * 128];         // W2[0] @ Ws1
__device__ float g_bc[3 * DD];            // b2[s] @ Wa1_s (+ ba1 for s==0)
__device__ float g_bsc[128];              // b2[0] @ Ws1 + bs1
__device__ float g_Sp[PSUM_ROWS * DD];    // partial sums of relu(u)
__device__ float g_pagg[AGG_BLOCKS * DD]; // partial agg (k-chunked matvec)

// grid-barrier state (generation-based; ctr self-resets -> graph-replay safe)
__device__ unsigned g_barctr = 0;
__device__ unsigned g_bargen = 0;

__device__ __forceinline__ void grid_barrier(unsigned total) {
    __threadfence();      // ALL threads: order prior global stores before arrive
    __syncthreads();
    if (threadIdx.x == 0) {
        volatile unsigned* genp = &g_bargen;
        const unsigned gen = *genp;
        if (atomicAdd(&g_barctr, 1u) == total - 1u) {
            g_barctr = 0;
            __threadfence();
            *genp = gen + 1u;
        } else {
            while (*genp == gen) {}
        }
        __threadfence();
    }
    __syncthreads();
}

// ---------------------------------------------------------------------------
// tf32 / cp.async helpers
// ---------------------------------------------------------------------------
__device__ __forceinline__ uint32_t f2tf32(float f) {
    uint32_t r;
    asm("cvt.rna.tf32.f32 %0, %1;" : "=r"(r) : "f"(f));
    return r;
}

__device__ __forceinline__ void mma_tf32(float* c, const uint32_t* a, const uint32_t* b) {
    asm volatile(
        "mma.sync.aligned.m16n8k8.row.col.f32.tf32.tf32.f32 "
        "{%0,%1,%2,%3},{%4,%5,%6,%7},{%8,%9},{%0,%1,%2,%3};\n"
        : "+f"(c[0]), "+f"(c[1]), "+f"(c[2]), "+f"(c[3])
        : "r"(a[0]), "r"(a[1]), "r"(a[2]), "r"(a[3]), "r"(b[0]), "r"(b[1]));
}

__device__ __forceinline__ void cp16(uint32_t saddr, const void* gaddr) {
    asm volatile("cp.async.cg.shared.global [%0], [%1], 16;\n"
                 :: "r"(saddr), "l"(gaddr));
}
__device__ __forceinline__ void cp_commit() {
    asm volatile("cp.async.commit_group;\n");
}
template <int N>
__device__ __forceinline__ void cp_wait() {
    asm volatile("cp.async.wait_group %0;\n" :: "n"(N));
}

// ---------------------------------------------------------------------------
// tf32 GEMM core, cp.async 4-stage pipeline. Block tile 128x128, BK=16,
// 256 threads (8 warps), warp tile 64x32. A: MxK fp32 row-major (lda = 256);
// B: KxN fp32 (ldb given). K = 256 fixed. EPI 0: C = A@B (+bias, opt relu).
// EPI 1: per-row score epilogue (hidden dim = 128 = full n-tile).
// ---------------------------------------------------------------------------
template<int EPI>
__device__ __forceinline__
void gemm_core(const float* __restrict__ A, const float* __restrict__ B,
               float* __restrict__ C, const float* __restrict__ bias,
               int M, int ldb, int ldc, int relu, int m0, int n0,
               float* __restrict__ sA, float* __restrict__ sB,
               const float* __restrict__ Ws2, const float* __restrict__ bsc,
               const float* __restrict__ bs2, float* __restrict__ out_sc,
               float* __restrict__ sred)
{
    const int tid  = threadIdx.x;
    const int lane = tid & 31;
    const int wid  = tid >> 5;      // 0..7
    const int wm = wid >> 2;        // 0..1 : 64-row slab
    const int wn = wid & 3;         // 0..3 : 32-col slab

    const uint32_t sA_u = (uint32_t)__cvta_generic_to_shared(sA);
    const uint32_t sB_u = (uint32_t)__cvta_generic_to_shared(sB);

    const int ac0 = tid, ac1 = tid + 256;
    const int ar0 = ac0 >> 2, ak0 = (ac0 & 3) * 4;
    const int ar1 = ac1 >> 2, ak1 = (ac1 & 3) * 4;
    const int garow0 = min(m0 + ar0, M - 1);
    const int garow1 = min(m0 + ar1, M - 1);
    const int bk0 = ac0 >> 5, bn0 = (ac0 & 31) * 4;
    const int bk1 = ac1 >> 5, bn1 = (ac1 & 31) * 4;

    auto issue = [&](int t, int s) {
        const int k0 = t * 16;
        cp16(sA_u + (s * A_TILE + ar0 * A_STRIDE + ak0) * 4,
             A + (long)garow0 * DD + k0 + ak0);
        cp16(sA_u + (s * A_TILE + ar1 * A_STRIDE + ak1) * 4,
             A + (long)garow1 * DD + k0 + ak1);
        cp16(sB_u + (s * B_TILE + bk0 * B_STRIDE + bn0) * 4,
             B + (long)(k0 + bk0) * ldb + n0 + bn0);
        cp16(sB_u + (s * B_TILE + bk1 * B_STRIDE + bn1) * 4,
             B + (long)(k0 + bk1) * ldb + n0 + bn1);
    };

    float acc[4][4][4];
    #pragma unroll
    for (int i = 0; i < 4; i++)
        #pragma unroll
        for (int j = 0; j < 4; j++)
            #pragma unroll
            for (int q = 0; q < 4; q++) acc[i][j][q] = 0.f;

    const int T = DD / 16;   // 16

    #pragma unroll
    for (int s = 0; s < NSTAGE - 1; s++) { issue(s, s); cp_commit(); }

    for (int t = 0; t < T; t++) {
        cp_wait<NSTAGE - 2>();
        __syncthreads();

        if (t + NSTAGE - 1 < T) issue(t + NSTAGE - 1, (t + NSTAGE - 1) % NSTAGE);
        cp_commit();

        const float* At = sA + (t % NSTAGE) * A_TILE;
        const float* Bt = sB + (t % NSTAGE) * B_TILE;

        #pragma unroll
        for (int kc = 0; kc < 2; kc++) {
            const int kk = kc * 8 + (lane & 3);
            uint32_t af[4][4], bf[4][2];
            #pragma unroll
            for (int mt = 0; mt < 4; mt++) {
                const int mr = wm * 64 + mt * 16 + (lane >> 2);
                af[mt][0] = f2tf32(At[mr * A_STRIDE + kk]);
                af[mt][1] = f2tf32(At[(mr + 8) * A_STRIDE + kk]);
                af[mt][2] = f2tf32(At[mr * A_STRIDE + kk + 4]);
                af[mt][3] = f2tf32(At[(mr + 8) * A_STRIDE + kk + 4]);
            }
            #pragma unroll
            for (int nt = 0; nt < 4; nt++) {
                const int nc = wn * 32 + nt * 8 + (lane >> 2);
                bf[nt][0] = f2tf32(Bt[kk * B_STRIDE + nc]);
                bf[nt][1] = f2tf32(Bt[(kk + 4) * B_STRIDE + nc]);
            }
            #pragma unroll
            for (int mt = 0; mt < 4; mt++)
                #pragma unroll
                for (int nt = 0; nt < 4; nt++)
                    mma_tf32(acc[mt][nt], af[mt], bf[nt]);
        }
        __syncthreads();
    }

    if (EPI == 0) {
        #pragma unroll
        for (int nt = 0; nt < 4; nt++) {
            const int c0 = n0 + wn * 32 + nt * 8 + (lane & 3) * 2;
            float bv0 = 0.f, bv1 = 0.f;
            if (bias) { bv0 = bias[c0]; bv1 = bias[c0 + 1]; }
            #pragma unroll
            for (int mt = 0; mt < 4; mt++) {
                const int r0 = m0 + wm * 64 + mt * 16 + (lane >> 2);
                const int r1 = r0 + 8;
                float v0 = acc[mt][nt][0] + bv0;
                float v1 = acc[mt][nt][1] + bv1;
                float v2 = acc[mt][nt][2] + bv0;
                float v3 = acc[mt][nt][3] + bv1;
                if (relu) {
                    v0 = fmaxf(v0, 0.f); v1 = fmaxf(v1, 0.f);
                    v2 = fmaxf(v2, 0.f); v3 = fmaxf(v3, 0.f);
                }
                if (r0 < M) *reinterpret_cast<float2*>(C + (long)r0 * ldc + c0) = make_float2(v0, v1);
                if (r1 < M) *reinterpret_cast<float2*>(C + (long)r1 * ldc + c0) = make_float2(v2, v3);
            }
        }
    } else {
        if (tid < 128) sred[tid] = 0.f;
        __syncthreads();
        #pragma unroll
        for (int mt = 0; mt < 4; mt++) {
            #pragma unroll
            for (int h = 0; h < 2; h++) {
                float part = 0.f;
                #pragma unroll
                for (int nt = 0; nt < 4; nt++) {
                    #pragma unroll
                    for (int b = 0; b < 2; b++) {
                        const int c = wn * 32 + nt * 8 + (lane & 3) * 2 + b;
                        part += fmaxf(acc[mt][nt][2 * h + b] + bsc[c], 0.f) * Ws2[c];
                    }
                }
                atomicAdd(&sred[wm * 64 + mt * 16 + (lane >> 2) + 8 * h], part);
            }
        }
        __syncthreads();
        if (tid < 128) {
            const int e = m0 + tid;
            if (e < M) {
                const float sc = 1.f / (1.f + expf(-(sred[tid] + bs2[0])));
                out_sc[e] = sc;
                #pragma unroll
                for (int j = 0; j < 4; j++)  out_sc[P3_OFF + e * 4 + j] = sc;
                #pragma unroll
                for (int k = 0; k < 16; k++) out_sc[P4_OFF + e * 16 + k] = sc;
            }
        }
    }
}

// ---------------------------------------------------------------------------
// Kernel 1 — Stage A: h1 = nf @ W1-chunks (96 tiles) | Wc[s] (12) | Wsc (2) |
//            bias precompute (1). 111 blocks.
// ---------------------------------------------------------------------------
__global__ __launch_bounds__(256, 2)
void stageA(const float* __restrict__ nf, const float* __restrict__ W1,
            const float* __restrict__ W2, const float* __restrict__ Wa1,
            const float* __restrict__ Ws1, const float* __restrict__ b2,
            const float* __restrict__ ba1, const float* __restrict__ bs1)
{
    extern __shared__ float smem[];
    float* sA = smem;
    float* sB = smem + NSTAGE * A_TILE;
    const int bz = blockIdx.x;

    if (bz < 96) {
        const int z = bz >> 4, r = bz & 15, x = r >> 1, y = r & 1;
        gemm_core<0>(nf, W1 + (long)z * DD * DD, g_h1 + (long)z * NN * DD, nullptr,
                     NN, DD, DD, 0, x * 128, y * 128, sA, sB,
                     nullptr, nullptr, nullptr, nullptr, nullptr);
    } else if (bz < 108) {
        const int i = bz - 96, z = i >> 2, r = i & 3, x = r >> 1, y = r & 1;
        gemm_core<0>(W2 + (long)z * DD * DD, Wa1 + (long)z * DD * DD,
                     g_Wc + (long)z * DD * DD, nullptr,
                     DD, DD, DD, 0, x * 128, y * 128, sA, sB,
                     nullptr, nullptr, nullptr, nullptr, nullptr);
    } else if (bz < 110) {
        const int x = bz - 108;
        gemm_core<0>(W2, Ws1, g_Wsc, nullptr,
                     DD, 128, 128, 0, x * 128, 0, sA, sB,
                     nullptr, nullptr, nullptr, nullptr, nullptr);
    } else {
        for (int g = threadIdx.x; g < 896; g += 256) {
            if (g < 768) {
                const int s = g >> 8, j = g & 255;
                float acc = (s == 0) ? ba1[j] : 0.f;
                for (int e = 0; e < DD; e++)
                    acc += b2[s * DD + e] * Wa1[((long)s * DD + e) * DD + j];
                g_bc[g] = acc;
            } else {
                const int j = g - 768;
                float acc = bs1[j];
                for (int e = 0; e < DD; e++)
                    acc += b2[e] * Ws1[e * 128 + j];
                g_bsc[j] = acc;
            }
        }
    }
}

// ---------------------------------------------------------------------------
// Kernel 2 — Stage B+H (224 blocks, all co-resident: 76KB smem -> 2/SM):
//   phase 1: H[s][e] = relu(h1[2s][src] + h1[2s+1][dst] + b1[s]), cooperative
//   grid barrier
//   phase 2: bz<192: G[s] tile GEMM | bz>=192: score tiles (fused epilogue)
// ---------------------------------------------------------------------------
#define BH_GRID 224

__global__ __launch_bounds__(256, 2)
void stageBH(const int* __restrict__ paths, const float* __restrict__ b1,
             const float* __restrict__ Ws2, const float* __restrict__ bs2,
             float* __restrict__ out_sc)
{
    extern __shared__ float smem[];
    float* sA = smem;
    float* sB = smem + NSTAGE * A_TILE;
    __shared__ float sred[128];
    const int bz = blockIdx.x;

    // ---- phase 1: cooperative H compute. 3*4000*64 float4 units.
    {
        const int total4 = 3 * NE * 64;   // 768000
        for (int u = bz * 256 + threadIdx.x; u < total4; u += BH_GRID * 256) {
            const int s  = u / (NE * 64);
            const int r  = u - s * (NE * 64);
            const int e  = r >> 6;
            const int c  = (r & 63) * 4;
            const int src = e >> 2;
            const int dst = paths[e * 4 + 1];
            const float4 a = *reinterpret_cast<const float4*>(g_h1 + ((long)(2 * s) * NN + src) * DD + c);
            const float4 b = *reinterpret_cast<const float4*>(g_h1 + ((long)(2 * s + 1) * NN + dst) * DD + c);
            const float4 bb = *reinterpret_cast<const float4*>(b1 + s * DD + c);
            float4 o;
            o.x = fmaxf(a.x + b.x + bb.x, 0.f);
            o.y = fmaxf(a.y + b.y + bb.y, 0.f);
            o.z = fmaxf(a.z + b.z + bb.z, 0.f);
            o.w = fmaxf(a.w + b.w + bb.w, 0.f);
            *reinterpret_cast<float4*>(g_H + ((long)s * NE + e) * DD + c) = o;
        }
    }
    grid_barrier(BH_GRID);

    // ---- phase 2: GEMM / score tiles
    if (bz < 192) {
        const int z = bz / 64, r = bz % 64, x = r >> 1, y = r & 1;
        gemm_core<0>(g_H + (long)z * NE * DD, g_Wc + (long)z * DD * DD,
                     g_G + (long)z * NE * DD, g_bc + z * DD,
                     NE, DD, DD, 0, x * 128, y * 128, sA, sB,
                     nullptr, nullptr, nullptr, nullptr, nullptr);
    } else {
        const int x = bz - 192;
        gemm_core<1>(g_H, g_Wsc, nullptr, nullptr,
                     NE, 128, 0, 0, x * 128, 0, sA, sB,
                     Ws2, g_bsc, bs2, out_sc, sred);
    }
}

// ---------------------------------------------------------------------------
// Kernel 3 — tail (500 blocks):
//   phase 1: path_sum (float4, 4 groups x 64 lanes; 8 e0 per block)
//   barrier; phase 2: agg (blocks 0..63, k-chunk 4; 32 row-iters w/ guard)
//   barrier; phase 3: update (blocks 0..249)
// ---------------------------------------------------------------------------
__device__ __forceinline__ void acc_relu4(float4& acc, float4 v) {
    acc.x += fmaxf(v.x, 0.f);
    acc.y += fmaxf(v.y, 0.f);
    acc.z += fmaxf(v.z, 0.f);
    acc.w += fmaxf(v.w, 0.f);
}
__device__ __forceinline__ float4 add4(float4 a, float4 b) {
    return make_float4(a.x + b.x, a.y + b.y, a.z + b.z, a.w + b.w);
}

__global__ void tail(const int* __restrict__ paths,
                     const float* __restrict__ Wa2,
                     const float* __restrict__ ba2,
                     const float* __restrict__ nf,
                     float* __restrict__ out)
{
    __shared__ int se1[8][4];
    __shared__ int se2b[8][4];
    const int t  = threadIdx.x;
    const int g  = t >> 6;        // group 0..3
    const int c4 = t & 63;        // float4 column index
    const int base = blockIdx.x * 8;

    // ---- phase 1: path_sum
    if (t < 32) {
        const int i = t >> 2, j = t & 3;
        const int e0 = base + i;
        const int e1 = paths[e0 * 4 + 1] * 4 + j;
        se1[i][j]  = e1;
        se2b[i][j] = paths[e1 * 4 + 1] * 4;
    }
    __syncthreads();

    const float4* G0 = reinterpret_cast<const float4*>(g_G);
    const float4* G1 = reinterpret_cast<const float4*>(g_G + (long)NE * DD);
    const float4* G2 = reinterpret_cast<const float4*>(g_G + (long)2 * NE * DD);

    float4 acc = make_float4(0.f, 0.f, 0.f, 0.f);
    #pragma unroll
    for (int ii = 0; ii < 2; ii++) {
        const int i = g * 2 + ii;
        const float4 a0 = G0[(long)(base + i) * 64 + c4];
        acc_relu4(acc, a0);
        #pragma unroll
        for (int j = 0; j < 4; j++) {
            const float4 a1 = add4(a0, G1[(long)se1[i][j] * 64 + c4]);
            acc_relu4(acc, a1);
            const int b2 = se2b[i][j];
            #pragma unroll
            for (int k = 0; k < 4; k++)
                acc_relu4(acc, add4(a1, G2[(long)(b2 + k) * 64 + c4]));
        }
    }
    reinterpret_cast<float4*>(g_Sp)[(long)(blockIdx.x * 4 + g) * 64 + c4] = acc;

    grid_barrier(PS_GRID);

    // ---- phase 2: agg, blocks 0..63 (k-chunks of 4).
    // 32 row-iterations with guard: covers ALL PSUM_ROWS=2000 rows
    // (rows 1984..1999 live in the guarded 32nd iteration — R10's bug).
    if (blockIdx.x < AGG_BLOCKS) {
        __shared__ float part[256];
        __shared__ float S_loc[4];
        const int kc = blockIdx.x;
        const int q     = t & 3;
        const int rbase = t >> 2;      // 0..63

        float sv = 0.f;
        #pragma unroll
        for (int i = 0; i < 32; i++) {
            const int r = rbase + 64 * i;   // up to 2047
            if (r < PSUM_ROWS)
                sv += g_Sp[(long)r * DD + kc * 4 + q];
        }
        part[t] = sv;
        __syncthreads();
        if (t < 4) {
            float s = 0.f;
            #pragma unroll
            for (int j = 0; j < 64; j++) s += part[t + 4 * j];
            S_loc[t] = s;
        }
        __syncthreads();
        float a = 0.f;
        #pragma unroll
        for (int q2 = 0; q2 < 4; q2++)
            a += S_loc[q2] * Wa2[(long)(kc * 4 + q2) * DD + t];
        g_pagg[kc * DD + t] = a;
    }

    grid_barrier(PS_GRID);

    // ---- phase 3: update, blocks 0..249
    if (blockIdx.x < 250) {
        __shared__ float agg[DD];
        float a = (float)PT * ba2[t];
        #pragma unroll
        for (int b = 0; b < AGG_BLOCKS; b++) a += g_pagg[b * DD + t];
        agg[t] = a;
        __syncthreads();

        const int i = blockIdx.x * 256 + t;   // float4 index, 64000 total
        if (i < (NN * DD) / 4) {
            float4 v = reinterpret_cast<const float4*>(nf)[i];
            const int c = (i * 4) & (DD - 1);
            v.x += agg[c + 0];
            v.y += agg[c + 1];
            v.z += agg[c + 2];
            v.w += agg[c + 3];
            reinterpret_cast<float4*>(out)[i] = v;
        }
    }
}

// ---------------------------------------------------------------------------
extern "C" void kernel_launch(void* const* d_in, const int* in_sizes, int n_in,
                              void* d_out, int out_size)
{
    const float* nf    = (const float*)d_in[0];
    const int*   paths = (const int*)  d_in[1];
    // d_in[2] = path_len (structure fixed -> masks derived from segment)
    const float* W1  = (const float*)d_in[3];
    const float* b1  = (const float*)d_in[4];
    const float* W2  = (const float*)d_in[5];
    const float* b2  = (const float*)d_in[6];
    const float* Ws1 = (const float*)d_in[7];
    const float* bs1 = (const float*)d_in[8];
    const float* Ws2 = (const float*)d_in[9];
    const float* bs2 = (const float*)d_in[10];
    const float* Wa1 = (const float*)d_in[11];
    const float* ba1 = (const float*)d_in[12];
    const float* Wa2 = (const float*)d_in[13];
    const float* ba2 = (const float*)d_in[14];

    float* out = (float*)d_out;   // [updated (1000*256) | scores (84000)]

    cudaFuncSetAttribute(stageA,  cudaFuncAttributeMaxDynamicSharedMemorySize, GEMM_SMEM);
    cudaFuncSetAttribute(stageBH, cudaFuncAttributeMaxDynamicSharedMemorySize, GEMM_SMEM);

    stageA<<<111, 256, GEMM_SMEM>>>(nf, W1, W2, Wa1, Ws1, b2, ba1, bs1);
    stageBH<<<BH_GRID, 256, GEMM_SMEM>>>(paths, b1, Ws2, bs2, out + NN * DD);
    tail<<<PS_GRID, 256>>>(paths, Wa2, ba2, nf, out);
}

// round 13
// speedup vs baseline: 1.6996x; 1.6996x over previous
#include <cuda_runtime.h>
#include <cstdint>

// Problem constants (fixed by reference)
#define NN   1000      // nodes
#define DD   256       // feature dim
#define NE   4000      // edges = N*K (== P2 block of paths)
#define P3_OFF 4000
#define P4_OFF 20000
#define PT   84000     // total paths
#define PS_GRID 500     // path_sum blocks (8 e0 each)
#define PSUM_ROWS 2000  // 4 partial rows per path_sum block
#define AGG_BLOCKS 64   // k-chunks of 4

// GEMM smem pipeline config
#define NSTAGE 4
#define A_STRIDE 20                 // floats per A smem row (16 + 4 pad)
#define B_STRIDE 136                // floats per B smem k-row (128 + 8 pad)
#define A_TILE (128 * A_STRIDE)     // 2560 floats / stage
#define B_TILE (16 * B_STRIDE)      // 2176 floats / stage
#define GEMM_SMEM ((NSTAGE * (A_TILE + B_TILE)) * 4)   // 75776 bytes

// Device scratch (static globals: no allocation allowed)
__device__ float g_h1[6 * NN * DD];       // nf @ W1 halves: [s*2+half][node][d]
__device__ float g_H[3 * NE * DD];        // relu(h_cur[src] + h_nxt[dst] + b1)
__device__ float g_G[3 * NE * DD];        // H_s @ Wc[s] + bc[s]
__device__ float g_Wc[3 * DD * DD];       // W2[s] @ Wa1_s
__device__ float g_Wsc[DD * 128];         // W2[0] @ Ws1
__device__ float g_bc[3 * DD];            // b2[s] @ Wa1_s (+ ba1 for s==0)
__device__ float g_bsc[128];              // b2[0] @ Ws1 + bs1
__device__ float g_Sp[PSUM_ROWS * DD];    // partial sums of relu(u)
__device__ float g_pagg[AGG_BLOCKS * DD]; // partial agg (k-chunked matvec)

// ---------------------------------------------------------------------------
// tf32 / cp.async helpers
// ---------------------------------------------------------------------------
__device__ __forceinline__ void mma_tf32(float* c, const uint32_t* a, const uint32_t* b) {
    asm volatile(
        "mma.sync.aligned.m16n8k8.row.col.f32.tf32.tf32.f32 "
        "{%0,%1,%2,%3},{%4,%5,%6,%7},{%8,%9},{%0,%1,%2,%3};\n"
        : "+f"(c[0]), "+f"(c[1]), "+f"(c[2]), "+f"(c[3])
        : "r"(a[0]), "r"(a[1]), "r"(a[2]), "r"(a[3]), "r"(b[0]), "r"(b[1]));
}

__device__ __forceinline__ void cp16(uint32_t saddr, const void* gaddr) {
    asm volatile("cp.async.cg.shared.global [%0], [%1], 16;\n"
                 :: "r"(saddr), "l"(gaddr));
}
__device__ __forceinline__ void cp_commit() {
    asm volatile("cp.async.commit_group;\n");
}
template <int N>
__device__ __forceinline__ void cp_wait() {
    asm volatile("cp.async.wait_group %0;\n" :: "n"(N));
}

// round-to-nearest tf32 via integer half-ulp add: HW truncates the low 13
// mantissa bits of a tf32 operand, so bits + 0x1000 (half of 2^13) gives
// round-half-up — unbiased (vs raw truncation's coherent -0.5ulp bias, which
// cost 2.1e-3 rel_err in R12). One IADD (alu pipe) vs ~20-cyc CVT.
__device__ __forceinline__ uint32_t rndtf32(float f) {
    return __float_as_uint(f) + 0x1000u;
}

// ---------------------------------------------------------------------------
// tf32 GEMM core, cp.async 4-stage pipeline. Block tile 128x128, BK=16,
// 256 threads (8 warps), warp tile 64x32. A: MxK fp32 row-major (lda = 256);
// B: KxN fp32 (ldb given). K = 256 fixed. EPI 0: C = A@B (+bias, opt relu).
// EPI 1: per-row score epilogue (hidden dim = 128 = full n-tile).
// ---------------------------------------------------------------------------
template<int EPI>
__device__ __forceinline__
void gemm_core(const float* __restrict__ A, const float* __restrict__ B,
               float* __restrict__ C, const float* __restrict__ bias,
               int M, int ldb, int ldc, int relu, int m0, int n0,
               float* __restrict__ sA, float* __restrict__ sB,
               const float* __restrict__ Ws2, const float* __restrict__ bsc,
               const float* __restrict__ bs2, float* __restrict__ out_sc,
               float* __restrict__ sred)
{
    const int tid  = threadIdx.x;
    const int lane = tid & 31;
    const int wid  = tid >> 5;      // 0..7
    const int wm = wid >> 2;        // 0..1 : 64-row slab
    const int wn = wid & 3;         // 0..3 : 32-col slab

    const uint32_t sA_u = (uint32_t)__cvta_generic_to_shared(sA);
    const uint32_t sB_u = (uint32_t)__cvta_generic_to_shared(sB);

    const int ac0 = tid, ac1 = tid + 256;
    const int ar0 = ac0 >> 2, ak0 = (ac0 & 3) * 4;
    const int ar1 = ac1 >> 2, ak1 = (ac1 & 3) * 4;
    const int garow0 = min(m0 + ar0, M - 1);
    const int garow1 = min(m0 + ar1, M - 1);
    const int bk0 = ac0 >> 5, bn0 = (ac0 & 31) * 4;
    const int bk1 = ac1 >> 5, bn1 = (ac1 & 31) * 4;

    auto issue = [&](int t, int s) {
        const int k0 = t * 16;
        cp16(sA_u + (s * A_TILE + ar0 * A_STRIDE + ak0) * 4,
             A + (long)garow0 * DD + k0 + ak0);
        cp16(sA_u + (s * A_TILE + ar1 * A_STRIDE + ak1) * 4,
             A + (long)garow1 * DD + k0 + ak1);
        cp16(sB_u + (s * B_TILE + bk0 * B_STRIDE + bn0) * 4,
             B + (long)(k0 + bk0) * ldb + n0 + bn0);
        cp16(sB_u + (s * B_TILE + bk1 * B_STRIDE + bn1) * 4,
             B + (long)(k0 + bk1) * ldb + n0 + bn1);
    };

    float acc[4][4][4];
    #pragma unroll
    for (int i = 0; i < 4; i++)
        #pragma unroll
        for (int j = 0; j < 4; j++)
            #pragma unroll
            for (int q = 0; q < 4; q++) acc[i][j][q] = 0.f;

    const int T = DD / 16;   // 16

    #pragma unroll
    for (int s = 0; s < NSTAGE - 1; s++) { issue(s, s); cp_commit(); }

    for (int t = 0; t < T; t++) {
        cp_wait<NSTAGE - 2>();
        __syncthreads();   // separates iter t-1 compute from this iter's issue

        if (t + NSTAGE - 1 < T) issue(t + NSTAGE - 1, (t + NSTAGE - 1) % NSTAGE);
        cp_commit();

        const float* At = sA + (t % NSTAGE) * A_TILE;
        const float* Bt = sB + (t % NSTAGE) * B_TILE;

        #pragma unroll
        for (int kc = 0; kc < 2; kc++) {
            const int kk = kc * 8 + (lane & 3);
            uint32_t af[4][4], bf[4][2];
            #pragma unroll
            for (int mt = 0; mt < 4; mt++) {
                const int mr = wm * 64 + mt * 16 + (lane >> 2);
                af[mt][0] = rndtf32(At[mr * A_STRIDE + kk]);
                af[mt][1] = rndtf32(At[(mr + 8) * A_STRIDE + kk]);
                af[mt][2] = rndtf32(At[mr * A_STRIDE + kk + 4]);
                af[mt][3] = rndtf32(At[(mr + 8) * A_STRIDE + kk + 4]);
            }
            #pragma unroll
            for (int nt = 0; nt < 4; nt++) {
                const int nc = wn * 32 + nt * 8 + (lane >> 2);
                bf[nt][0] = rndtf32(Bt[kk * B_STRIDE + nc]);
                bf[nt][1] = rndtf32(Bt[(kk + 4) * B_STRIDE + nc]);
            }
            #pragma unroll
            for (int mt = 0; mt < 4; mt++)
                #pragma unroll
                for (int nt = 0; nt < 4; nt++)
                    mma_tf32(acc[mt][nt], af[mt], bf[nt]);
        }
        // no trailing sync needed: next iteration's top sync orders
        // this compute (reads buf t%4) before issue into (t+4)%4 == t%4.
    }

    if (EPI == 0) {
        #pragma unroll
        for (int nt = 0; nt < 4; nt++) {
            const int c0 = n0 + wn * 32 + nt * 8 + (lane & 3) * 2;
            float bv0 = 0.f, bv1 = 0.f;
            if (bias) { bv0 = bias[c0]; bv1 = bias[c0 + 1]; }
            #pragma unroll
            for (int mt = 0; mt < 4; mt++) {
                const int r0 = m0 + wm * 64 + mt * 16 + (lane >> 2);
                const int r1 = r0 + 8;
                float v0 = acc[mt][nt][0] + bv0;
                float v1 = acc[mt][nt][1] + bv1;
                float v2 = acc[mt][nt][2] + bv0;
                float v3 = acc[mt][nt][3] + bv1;
                if (relu) {
                    v0 = fmaxf(v0, 0.f); v1 = fmaxf(v1, 0.f);
                    v2 = fmaxf(v2, 0.f); v3 = fmaxf(v3, 0.f);
                }
                if (r0 < M) *reinterpret_cast<float2*>(C + (long)r0 * ldc + c0) = make_float2(v0, v1);
                if (r1 < M) *reinterpret_cast<float2*>(C + (long)r1 * ldc + c0) = make_float2(v2, v3);
            }
        }
    } else {
        if (tid < 128) sred[tid] = 0.f;
        __syncthreads();
        #pragma unroll
        for (int mt = 0; mt < 4; mt++) {
            #pragma unroll
            for (int h = 0; h < 2; h++) {
                float part = 0.f;
                #pragma unroll
                for (int nt = 0; nt < 4; nt++) {
                    #pragma unroll
                    for (int b = 0; b < 2; b++) {
                        const int c = wn * 32 + nt * 8 + (lane & 3) * 2 + b;
                        part += fmaxf(acc[mt][nt][2 * h + b] + bsc[c], 0.f) * Ws2[c];
                    }
                }
                atomicAdd(&sred[wm * 64 + mt * 16 + (lane >> 2) + 8 * h], part);
            }
        }
        __syncthreads();
        if (tid < 128) {
            const int e = m0 + tid;
            if (e < M) {
                const float sc = 1.f / (1.f + expf(-(sred[tid] + bs2[0])));
                out_sc[e] = sc;
                #pragma unroll
                for (int j = 0; j < 4; j++)  out_sc[P3_OFF + e * 4 + j] = sc;
                #pragma unroll
                for (int k = 0; k < 16; k++) out_sc[P4_OFF + e * 16 + k] = sc;
            }
        }
    }
}

// ---------------------------------------------------------------------------
// Stage A: h1 = nf @ W1-chunks (96 tiles) | Wc[s] = W2[s]@Wa1_s (12) |
//          Wsc = W2[0]@Ws1 (2) | bias precompute (1).  111 blocks.
// ---------------------------------------------------------------------------
__global__ __launch_bounds__(256, 2)
void stageA(const float* __restrict__ nf, const float* __restrict__ W1,
            const float* __restrict__ W2, const float* __restrict__ Wa1,
            const float* __restrict__ Ws1, const float* __restrict__ b2,
            const float* __restrict__ ba1, const float* __restrict__ bs1)
{
    extern __shared__ float smem[];
    float* sA = smem;
    float* sB = smem + NSTAGE * A_TILE;
    const int bz = blockIdx.x;

    if (bz < 96) {
        const int z = bz >> 4, r = bz & 15, x = r >> 1, y = r & 1;
        gemm_core<0>(nf, W1 + (long)z * DD * DD, g_h1 + (long)z * NN * DD, nullptr,
                     NN, DD, DD, 0, x * 128, y * 128, sA, sB,
                     nullptr, nullptr, nullptr, nullptr, nullptr);
    } else if (bz < 108) {
        const int i = bz - 96, z = i >> 2, r = i & 3, x = r >> 1, y = r & 1;
        gemm_core<0>(W2 + (long)z * DD * DD, Wa1 + (long)z * DD * DD,
                     g_Wc + (long)z * DD * DD, nullptr,
                     DD, DD, DD, 0, x * 128, y * 128, sA, sB,
                     nullptr, nullptr, nullptr, nullptr, nullptr);
    } else if (bz < 110) {
        const int x = bz - 108;
        gemm_core<0>(W2, Ws1, g_Wsc, nullptr,
                     DD, 128, 128, 0, x * 128, 0, sA, sB,
                     nullptr, nullptr, nullptr, nullptr, nullptr);
    } else {
        for (int g = threadIdx.x; g < 896; g += 256) {
            if (g < 768) {
                const int s = g >> 8, j = g & 255;
                float acc = (s == 0) ? ba1[j] : 0.f;
                for (int e = 0; e < DD; e++)
                    acc += b2[s * DD + e] * Wa1[((long)s * DD + e) * DD + j];
                g_bc[g] = acc;
            } else {
                const int j = g - 768;
                float acc = bs1[j];
                for (int e = 0; e < DD; e++)
                    acc += b2[e] * Ws1[e * 128 + j];
                g_bsc[j] = acc;
            }
        }
    }
}

// ---------------------------------------------------------------------------
// Stage H: H[s][e] = relu(h1[2s][src(e)] + h1[2s+1][dst(e)] + b1[s])
// ---------------------------------------------------------------------------
__global__ void stageH(const int* __restrict__ paths, const float* __restrict__ b1)
{
    const int s = blockIdx.y;
    const int r = threadIdx.x >> 6;
    const int c = (threadIdx.x & 63) * 4;
    const int e = blockIdx.x * 4 + r;
    const int src = e >> 2;
    const int dst = paths[e * 4 + 1];

    const float4 a = *reinterpret_cast<const float4*>(g_h1 + ((long)(2 * s) * NN + src) * DD + c);
    const float4 b = *reinterpret_cast<const float4*>(g_h1 + ((long)(2 * s + 1) * NN + dst) * DD + c);
    const float4 bb = *reinterpret_cast<const float4*>(b1 + s * DD + c);
    float4 o;
    o.x = fmaxf(a.x + b.x + bb.x, 0.f);
    o.y = fmaxf(a.y + b.y + bb.y, 0.f);
    o.z = fmaxf(a.z + b.z + bb.z, 0.f);
    o.w = fmaxf(a.w + b.w + bb.w, 0.f);
    *reinterpret_cast<float4*>(g_H + ((long)s * NE + e) * DD + c) = o;
}

// ---------------------------------------------------------------------------
// Stage B: G[s] = H[s] @ Wc[s] + bc[s] (192 tiles) |
//          scores: H[0] @ Wsc -> relu -> dot Ws2 -> sigmoid -> scatter (32).
// ---------------------------------------------------------------------------
__global__ __launch_bounds__(256, 2)
void stageB(const float* __restrict__ Ws2, const float* __restrict__ bs2,
            float* __restrict__ out_sc)
{
    extern __shared__ float smem[];
    float* sA = smem;
    float* sB = smem + NSTAGE * A_TILE;
    __shared__ float sred[128];
    const int bz = blockIdx.x;

    if (bz < 192) {
        const int z = bz / 64, r = bz % 64, x = r >> 1, y = r & 1;
        gemm_core<0>(g_H + (long)z * NE * DD, g_Wc + (long)z * DD * DD,
                     g_G + (long)z * NE * DD, g_bc + z * DD,
                     NE, DD, DD, 0, x * 128, y * 128, sA, sB,
                     nullptr, nullptr, nullptr, nullptr, nullptr);
    } else {
        const int x = bz - 192;
        gemm_core<1>(g_H, g_Wsc, nullptr, nullptr,
                     NE, 128, 0, 0, x * 128, 0, sA, sB,
                     Ws2, g_bsc, bs2, out_sc, sred);
    }
}

// ---------------------------------------------------------------------------
// Path reduce, float4: 256 threads = 4 groups x 64 lanes; lane owns a float4
// column slice; group walks 2 of the block's 8 e0-trees.
// ---------------------------------------------------------------------------
__device__ __forceinline__ void acc_relu4(float4& acc, float4 v) {
    acc.x += fmaxf(v.x, 0.f);
    acc.y += fmaxf(v.y, 0.f);
    acc.z += fmaxf(v.z, 0.f);
    acc.w += fmaxf(v.w, 0.f);
}
__device__ __forceinline__ float4 add4(float4 a, float4 b) {
    return make_float4(a.x + b.x, a.y + b.y, a.z + b.z, a.w + b.w);
}

__global__ void path_sum(const int* __restrict__ paths)
{
    __shared__ int se1[8][4];
    __shared__ int se2b[8][4];
    const int t  = threadIdx.x;
    const int g  = t >> 6;        // group 0..3
    const int c4 = t & 63;        // float4 column index
    const int base = blockIdx.x * 8;

    if (t < 32) {
        const int i = t >> 2, j = t & 3;
        const int e0 = base + i;
        const int e1 = paths[e0 * 4 + 1] * 4 + j;
        se1[i][j]  = e1;
        se2b[i][j] = paths[e1 * 4 + 1] * 4;
    }
    __syncthreads();

    const float4* G0 = reinterpret_cast<const float4*>(g_G);
    const float4* G1 = reinterpret_cast<const float4*>(g_G + (long)NE * DD);
    const float4* G2 = reinterpret_cast<const float4*>(g_G + (long)2 * NE * DD);

    float4 acc = make_float4(0.f, 0.f, 0.f, 0.f);
    #pragma unroll
    for (int ii = 0; ii < 2; ii++) {
        const int i = g * 2 + ii;
        const float4 a0 = G0[(long)(base + i) * 64 + c4];
        acc_relu4(acc, a0);
        #pragma unroll
        for (int j = 0; j < 4; j++) {
            const float4 a1 = add4(a0, G1[(long)se1[i][j] * 64 + c4]);
            acc_relu4(acc, a1);
            const int b2 = se2b[i][j];
            #pragma unroll
            for (int k = 0; k < 4; k++)
                acc_relu4(acc, add4(a1, G2[(long)(b2 + k) * 64 + c4]));
        }
    }
    reinterpret_cast<float4*>(g_Sp)[(long)(blockIdx.x * 4 + g) * 64 + c4] = acc;
}

// ---------------------------------------------------------------------------
// Parallel agg, k-chunked: block kc owns k in [kc*4, kc*4+4). Guarded 32
// row-iterations cover ALL PSUM_ROWS=2000 rows.
// ---------------------------------------------------------------------------
__global__ void final_agg_par(const float* __restrict__ Wa2)
{
    __shared__ float part[256];
    __shared__ float S_loc[4];
    const int t  = threadIdx.x;
    const int kc = blockIdx.x;
    const int q     = t & 3;       // column within chunk
    const int rbase = t >> 2;      // 0..63

    float sv = 0.f;
    #pragma unroll
    for (int i = 0; i < 32; i++) {
        const int r = rbase + 64 * i;   // up to 2047
        if (r < PSUM_ROWS)
            sv += g_Sp[(long)r * DD + kc * 4 + q];
    }
    part[t] = sv;
    __syncthreads();

    if (t < 4) {
        float s = 0.f;
        #pragma unroll
        for (int j = 0; j < 64; j++) s += part[t + 4 * j];
        S_loc[t] = s;
    }
    __syncthreads();

    float a = 0.f;
    #pragma unroll
    for (int q2 = 0; q2 < 4; q2++)
        a += S_loc[q2] * Wa2[(long)(kc * 4 + q2) * DD + t];
    g_pagg[kc * DD + t] = a;
}

// ---------------------------------------------------------------------------
// Final update: reduce g_pagg (+PT*ba2) into smem agg, broadcast-add to nf.
// ---------------------------------------------------------------------------
__global__ void final_update(const float* __restrict__ nf,
                             const float* __restrict__ ba2,
                             float* __restrict__ out)
{
    __shared__ float agg[DD];
    const int t = threadIdx.x;

    float a = (float)PT * ba2[t];
    #pragma unroll
    for (int b = 0; b < AGG_BLOCKS; b++) a += g_pagg[b * DD + t];
    agg[t] = a;
    __syncthreads();

    const int i = blockIdx.x * 256 + t;   // float4 index, 64000 total
    if (i < (NN * DD) / 4) {
        float4 v = reinterpret_cast<const float4*>(nf)[i];
        const int c = (i * 4) & (DD - 1);
        v.x += agg[c + 0];
        v.y += agg[c + 1];
        v.z += agg[c + 2];
        v.w += agg[c + 3];
        reinterpret_cast<float4*>(out)[i] = v;
    }
}

// ---------------------------------------------------------------------------
extern "C" void kernel_launch(void* const* d_in, const int* in_sizes, int n_in,
                              void* d_out, int out_size)
{
    const float* nf    = (const float*)d_in[0];
    const int*   paths = (const int*)  d_in[1];
    // d_in[2] = path_len (structure fixed -> masks derived from segment)
    const float* W1  = (const float*)d_in[3];
    const float* b1  = (const float*)d_in[4];
    const float* W2  = (const float*)d_in[5];
    const float* b2  = (const float*)d_in[6];
    const float* Ws1 = (const float*)d_in[7];
    const float* bs1 = (const float*)d_in[8];
    const float* Ws2 = (const float*)d_in[9];
    const float* bs2 = (const float*)d_in[10];
    const float* Wa1 = (const float*)d_in[11];
    const float* ba1 = (const float*)d_in[12];
    const float* Wa2 = (const float*)d_in[13];
    const float* ba2 = (const float*)d_in[14];

    float* out = (float*)d_out;   // [updated (1000*256) | scores (84000)]

    cudaFuncSetAttribute(stageA, cudaFuncAttributeMaxDynamicSharedMemorySize, GEMM_SMEM);
    cudaFuncSetAttribute(stageB, cudaFuncAttributeMaxDynamicSharedMemorySize, GEMM_SMEM);

    stageA<<<111, 256, GEMM_SMEM>>>(nf, W1, W2, Wa1, Ws1, b2, ba1, bs1);
    stageH<<<dim3(NN, 3), 256>>>(paths, b1);
    stageB<<<224, 256, GEMM_SMEM>>>(Ws2, bs2, out + NN * DD);
    path_sum<<<PS_GRID, 256>>>(paths);
    final_agg_par<<<AGG_BLOCKS, 256>>>(Wa2);
    final_update<<<(NN * DD / 4 + 255) / 256, 256>>>(nf, ba2, out);
}